// round 16
// baseline (speedup 1.0000x reference)
#include <cuda_runtime.h>
#include <cuda_bf16.h>
#include <math.h>
#include <stdint.h>

#define Bm 64
#define Tm 512
#define Hm 512
#define Cm 64
#define NBLK 128
#define NTHR 512
#define KC 128
#define KHP 136                // padded smem row stride (bf16), ==8 mod 64
#define S_WHI 0
#define S_WLO (32*KHP)
#define S_HHI (64*KHP)
#define S_HLO (128*KHP)
#define SLOT_BF (192*KHP)
#define NSLOT 3
#define F_SG   39168
#define F_CS   (F_SG + 4*2048)
#define F_B1   (F_CS + 1024)
#define F_B2   (F_B1 + 32)
#define F_XW   (F_B2 + 32)
#define SM_FLOATS (F_XW + 32)
#define SM_BYTES (SM_FLOATS*4)
#define SQ 260
#define FC_SMB (128*SQ*4)

__device__ __nv_bfloat16 gWh[6][64][32*512];
__device__ __nv_bfloat16 gWl[6][64][32*512];
__device__ __nv_bfloat16 gH1h[2][2][Bm*Hm], gH1l[2][2][Bm*Hm];
__device__ __nv_bfloat16 gH2h[2][2][Bm*Hm], gH2l[2][2][Bm*Hm];
__device__ __nv_bfloat16 gC1h[2][Bm*Hm],    gC1l[2][Bm*Hm];
__device__ float g_hist[2][Tm][Bm*Hm];
__device__ unsigned g_cnt2[2] = {0, 0};
__device__ unsigned g_gen = 0;

__device__ __forceinline__ float sigf(float v){ return 1.f/(1.f+expf(-v)); }
__device__ __forceinline__ void fma4(float s, const float4 v, float4& a){
    a.x=fmaf(s,v.x,a.x); a.y=fmaf(s,v.y,a.y); a.z=fmaf(s,v.z,a.z); a.w=fmaf(s,v.w,a.w);
}
__device__ __forceinline__ int jrow(int r, int hcb){ return ((r>>3)<<9) + hcb + (r&7); }

__device__ __forceinline__ void ev_arrive(int par){
    __threadfence(); __syncthreads();
    if (threadIdx.x == 0) {
        if (atomicAdd(&g_cnt2[par],1u) == NBLK-1) { g_cnt2[par]=0; __threadfence(); atomicAdd(&g_gen,1u); }
    }
}
__device__ __forceinline__ void ev_wait(unsigned base, unsigned n){
    if (threadIdx.x == 0) { while ((int)(*(volatile unsigned*)&g_gen - base) < (int)n) {} __threadfence(); }
    __syncthreads();
}
__device__ __forceinline__ unsigned smaddr(const void* p){
    unsigned a; asm("{.reg .u64 t; cvta.to.shared.u64 t,%1; cvt.u32.u64 %0,t;}":"=r"(a):"l"(p)); return a;
}
__device__ __forceinline__ void cpa16(unsigned d, const void* s){
    asm volatile("cp.async.cg.shared.global [%0],[%1],16;"::"r"(d),"l"(s));
}
#define CP_COMMIT() asm volatile("cp.async.commit_group;")
#define CP_WAIT1()  asm volatile("cp.async.wait_group 1;" ::: "memory")

__device__ __forceinline__ void ldsm4(uint4& d, unsigned a){
    asm volatile("ldmatrix.sync.aligned.m8n8.x4.shared.b16 {%0,%1,%2,%3},[%4];"
        : "=r"(d.x), "=r"(d.y), "=r"(d.z), "=r"(d.w) : "r"(a));
}
__device__ __forceinline__ void mma16816(float4& c, const uint4 a, const uint2 b){
    asm volatile("mma.sync.aligned.m16n8k16.row.col.f32.bf16.bf16.f32 "
        "{%0,%1,%2,%3},{%4,%5,%6,%7},{%8,%9},{%0,%1,%2,%3};"
        : "+f"(c.x), "+f"(c.y), "+f"(c.z), "+f"(c.w)
        : "r"(a.x), "r"(a.y), "r"(a.z), "r"(a.w), "r"(b.x), "r"(b.y));
}

// branch-free staging: 512 threads, row = (tid>>4) + 32*i, region compile-time per i
__device__ __forceinline__ void pf_chunk(__nv_bfloat16* sb, int slot,
        const __nv_bfloat16* wh, const __nv_bfloat16* wl,
        const __nv_bfloat16* hh, const __nv_bfloat16* hl, int k0, int r, int cc8){
    unsigned db = smaddr(sb) + slot*(SLOT_BF*2);
    int rk2 = (r*KHP + cc8)*2;
    int so = r*512 + cc8 + k0;
    cpa16(db + S_WHI*2 + rk2, wh + so);
    cpa16(db + S_WLO*2 + rk2, wl + so);
    cpa16(db + S_HHI*2 + rk2, hh + so);
    cpa16(db + S_HHI*2 + 32*KHP*2 + rk2, hh + so + 32*512);
    cpa16(db + S_HLO*2 + rk2, hl + so);
    cpa16(db + S_HLO*2 + 32*KHP*2 + rk2, hl + so + 32*512);
    CP_COMMIT();
}

// one K=128 chunk; warp = M32 x N16 at n-offset nb, k-group kg
__device__ __forceinline__ void gemm_chunk(const __nv_bfloat16* sb, int kg, int nb,
                                           int lane, float4 C[2][2]){
    const int aRow = lane & 15, aK = (lane >> 4) * 8;
    const int bRow = ((lane >> 4) << 3) + (lane & 7), bK = ((lane >> 3) & 1) * 8;
#pragma unroll
    for (int k2 = 0; k2 < 2; ++k2) {
        int kk = (kg*2 + k2)*16;
        uint4 Ah[2], Al[2], Bh, Bl;
#pragma unroll
        for (int i = 0; i < 2; ++i) {
            unsigned pa = smaddr(sb + S_WHI + (16*i + aRow)*KHP + kk + aK);
            ldsm4(Ah[i], pa);
            ldsm4(Al[i], pa + (S_WLO - S_WHI)*2);
        }
        {
            unsigned pb = smaddr(sb + S_HHI + (nb + bRow)*KHP + kk + bK);
            ldsm4(Bh, pb);
            ldsm4(Bl, pb + (S_HLO - S_HHI)*2);
        }
        uint2 bh0 = make_uint2(Bh.x, Bh.y), bh1 = make_uint2(Bh.z, Bh.w);
        uint2 bl0 = make_uint2(Bl.x, Bl.y), bl1 = make_uint2(Bl.z, Bl.w);
#pragma unroll
        for (int i = 0; i < 2; ++i) {
            mma16816(C[i][0], Ah[i], bh0);
            mma16816(C[i][0], Ah[i], bl0);
            mma16816(C[i][0], Al[i], bh0);
            mma16816(C[i][1], Ah[i], bh1);
            mma16816(C[i][1], Ah[i], bl1);
            mma16816(C[i][1], Al[i], bh1);
        }
    }
}

__device__ __forceinline__ void store_C(float* sg, float4 C[2][2], int kg, int nb, int lg, int tg){
#pragma unroll
    for (int i = 0; i < 2; ++i)
#pragma unroll
        for (int nt = 0; nt < 2; ++nt) {
            float* s = sg + kg*2048 + (16*i + lg)*64 + nb + nt*8 + 2*tg;
            *(float2*)s = make_float2(C[i][nt].x, C[i][nt].y);
            *(float2*)(s + 512) = make_float2(C[i][nt].z, C[i][nt].w);
        }
}

// one (hc, b) element per thread (512 = 8 hc x 64 b)
__device__ __forceinline__ void cell_phase(float* smf, int tid, int hcb,
        const float* sbias, const float* swih, const float* x, int te,
        float* cstate, __nv_bfloat16* ph_hi, __nv_bfloat16* ph_lo,
        __nv_bfloat16* pc_hi, __nv_bfloat16* pc_lo, float* hist){
    float* sg = smf + F_SG;
    int b = tid & 63, hc = tid >> 6;
    float gs[4];
#pragma unroll
    for (int g = 0; g < 4; ++g) {
        int r = g*8 + hc;
        float v = sg[r*64+b] + sg[2048 + r*64+b] + sg[4096 + r*64+b] + sg[6144 + r*64+b] + sbias[r];
        if (swih) v = fmaf(swih[r], __ldg(x + b*Tm + te), v);
        gs[g] = v;
    }
    float co = cstate[hc*64 + b];
    float cn = sigf(gs[1])*co + sigf(gs[0])*tanhf(gs[2]);
    cstate[hc*64 + b] = cn;
    float hv = sigf(gs[3])*tanhf(cn);
    int off = b*512 + hcb + hc;
    __nv_bfloat16 a0 = __float2bfloat16(hv);
    ph_hi[off] = a0;
    ph_lo[off] = __float2bfloat16(hv - __bfloat162float(a0));
    if (pc_hi) {
        __nv_bfloat16 c0 = __float2bfloat16(cn);
        pc_hi[off] = c0;
        pc_lo[off] = __float2bfloat16(cn - __bfloat162float(c0));
    }
    if (hist) hist[off] = cn;
}

__global__ void noop_kernel() {}

extern "C" __global__ void __launch_bounds__(NTHR, 1)
lstm_persist(const float* __restrict__ x,
             const float* wih1, const float* whh1, const float* bih1, const float* bhh1,
             const float* wih2, const float* whh2, const float* bih2, const float* bhh2,
             const float* wih3, const float* whh3, const float* bih3, const float* bhh3,
             const float* wih4, const float* whh4, const float* bih4, const float* bhh4) {
    extern __shared__ __align__(16) float smf[];
    __nv_bfloat16* sb = (__nv_bfloat16*)smf;

    const int tid = threadIdx.x;
    const int dir = blockIdx.x & 1;
    const int gb  = blockIdx.x >> 1;
    const int hcb = gb << 3;
    const unsigned gbase = *(volatile unsigned*)&g_gen;

    const float* WIH1 = dir ? wih3 : wih1;
    const float* BIH1 = dir ? bih3 : bih1;
    const float* BHH1 = dir ? bhh3 : bhh1;
    const float* BIH2 = dir ? bih4 : bih2;
    const float* BHH2 = dir ? bhh4 : bhh2;
    const float* Wsrc[3] = { dir ? whh3 : whh1, dir ? whh4 : whh2, dir ? wih4 : wih2 };

    if (tid < 32) {
        int j = jrow(tid, hcb);
        smf[F_B1 + tid] = __ldg(BIH1 + j) + __ldg(BHH1 + j);
        smf[F_B2 + tid] = __ldg(BIH2 + j) + __ldg(BHH2 + j);
        smf[F_XW + tid] = __ldg(WIH1 + j);
    }
    for (int i = tid; i < 1024; i += NTHR) smf[F_CS + i] = 0.f;
#pragma unroll 1
    for (int p = 0; p < 3; ++p) {
        int pidx = dir*3 + p;
        for (int idx = tid; idx < 32*512; idx += NTHR) {
            int r = idx >> 9, k = idx & 511;
            float v = __ldg(Wsrc[p] + (size_t)jrow(r, hcb)*512 + k);
            __nv_bfloat16 hi = __float2bfloat16(v);
            gWh[pidx][gb][idx] = hi;
            gWl[pidx][gb][idx] = __float2bfloat16(v - __bfloat162float(hi));
        }
    }
    {
        const int gt = blockIdx.x*NTHR + tid, stride = NBLK*NTHR;
        unsigned* z[4] = { (unsigned*)gH1h, (unsigned*)gH1l, (unsigned*)gH2h, (unsigned*)gH2l };
        for (int a = 0; a < 4; ++a)
            for (int i = gt; i < 2*2*Bm*Hm/2; i += stride) z[a][i] = 0u;
    }
    ev_arrive(1);
    ev_wait(gbase, 1);

    const int lane = tid & 31, wid = tid >> 5;
    const int kg = wid >> 2, nb = (wid & 3) * 16;
    const int lg = lane >> 2, tg = lane & 3;
    const int pr = tid >> 4, pc8 = (tid & 15) * 8;   // staging row/col

    const __nv_bfloat16* wH[3]; const __nv_bfloat16* wL[3];
#pragma unroll
    for (int p = 0; p < 3; ++p) { wH[p] = gWh[dir*3+p][gb]; wL[p] = gWl[dir*3+p][gb]; }

    pf_chunk(sb, 0, wH[0], wL[0], gH1h[dir][1], gH1l[dir][1], 0,  pr, pc8);
    pf_chunk(sb, 1, wH[0], wL[0], gH1h[dir][1], gH1l[dir][1], KC, pr, pc8);

    float4 C[2][2];
#pragma unroll
    for (int i = 0; i < 2; ++i)
#pragma unroll
        for (int nt = 0; nt < 2; ++nt) C[i][nt] = make_float4(0,0,0,0);

#pragma unroll 1
    for (int t = 0; t < Tm; ++t) {
        const int wb = t & 1, rb = wb ^ 1;
        const int te = dir ? (Tm - 1 - t) : t;
        const __nv_bfloat16* hH[3] = { gH1h[dir][rb], gH2h[dir][rb], gC1h[dir] };
        const __nv_bfloat16* hL[3] = { gH1l[dir][rb], gH2l[dir][rb], gC1l[dir] };

#pragma unroll 1
        for (int g = 0; g < 12; ++g) {
            CP_WAIT1(); __syncthreads();
            if (g == 2) ev_wait(gbase, 2u*t + 1u);
            if (g == 6) ev_wait(gbase, 2u*t + 2u);
            int n = g + 2;
            if (n < 12)
                pf_chunk(sb, n % NSLOT, wH[n>>2], wL[n>>2], hH[n>>2], hL[n>>2], (n & 3)*KC, pr, pc8);
            else if (t + 1 < Tm)
                pf_chunk(sb, n % NSLOT, wH[0], wL[0], gH1h[dir][wb], gH1l[dir][wb], (n-12)*KC, pr, pc8);
            gemm_chunk(sb + (g % NSLOT)*SLOT_BF, kg, nb, lane, C);

            if (g == 3) {
                store_C(smf + F_SG, C, kg, nb, lg, tg);
                __syncthreads();
                cell_phase(smf, tid, hcb, smf + F_B1, smf + F_XW, x, te,
                           smf + F_CS, gH1h[dir][wb], gH1l[dir][wb],
                           gC1h[dir], gC1l[dir], (float*)0);
#pragma unroll
                for (int i = 0; i < 2; ++i)
#pragma unroll
                    for (int nt = 0; nt < 2; ++nt) C[i][nt] = make_float4(0,0,0,0);
                ev_arrive(0);
            }
            if (g == 11) {
                store_C(smf + F_SG, C, kg, nb, lg, tg);
                __syncthreads();
                cell_phase(smf, tid, hcb, smf + F_B2, (const float*)0, x, te,
                           smf + F_CS + 512, gH2h[dir][wb], gH2l[dir][wb],
                           (__nv_bfloat16*)0, (__nv_bfloat16*)0, g_hist[dir][t]);
#pragma unroll
                for (int i = 0; i < 2; ++i)
#pragma unroll
                    for (int nt = 0; nt < 2; ++nt) C[i][nt] = make_float4(0,0,0,0);
                ev_arrive(1);
            }
        }
    }
    ev_wait(gbase, 2u*Tm + 1u);
}

// ---- final FC (unchanged) ----
__device__ __forceinline__ void stage_T(const float* __restrict__ src,
                                        float* __restrict__ sT, int tid) {
#pragma unroll
    for (int it = 0; it < 32; ++it) {
        int id = tid + 256*it;
        int lane = id & 31, grp = id >> 5;
        int kl = lane & 7, bg = lane >> 3;
        int kq = ((grp & 15) << 3) | kl;
        int b  = ((grp >> 4) << 2) | bg;
        float4 v = __ldcg((const float4*)(src + b*Hm + (kq << 2)));
        float* p = sT + kq*SQ + b;
        p[0] = v.x; p[64] = v.y; p[128] = v.z; p[192] = v.w;
    }
}

extern "C" __global__ void __launch_bounds__(256)
fc_kernel(const float* __restrict__ fcw, const float* __restrict__ fcb,
          const float* __restrict__ bfcw, const float* __restrict__ bfcb,
          float* __restrict__ out) {
    extern __shared__ __align__(16) float smq[];
    float* sT = smq;
    const int tid = threadIdx.x;
    const int d = blockIdx.x >> 9;
    const int t = blockIdx.x & 511;
    const float* W = d ? bfcw : fcw;
    const float* bias = d ? bfcb : fcb;

    stage_T(W, sT, tid);
    __syncthreads();

    const float* hb = g_hist[d][t];
    const size_t obase = (size_t)d*Bm*Tm*Cm + (size_t)t*Cm;
#pragma unroll
    for (int tt = 0; tt < 4; ++tt) {
        int tile = tid + 256*tt;
        int b = tile >> 4;
        int c0 = (tile & 15) << 2;
        float4 acc = *(const float4*)(bias + c0);
        const float4* hq = (const float4*)(hb + b*Hm);
        const float* wq0 = sT + c0;
#pragma unroll 4
        for (int kq = 0; kq < 128; ++kq) {
            float4 h4 = __ldg(hq + kq);
            const float* wq = wq0 + kq*SQ;
            fma4(h4.x, *(const float4*)(wq), acc);
            fma4(h4.y, *(const float4*)(wq + 64), acc);
            fma4(h4.z, *(const float4*)(wq + 128), acc);
            fma4(h4.w, *(const float4*)(wq + 192), acc);
        }
        *(float4*)(out + obase + (size_t)b*Tm*Cm + c0) = acc;
    }
}

extern "C" void kernel_launch(void* const* d_in, const int* in_sizes, int n_in,
                              void* d_out, int out_size) {
    const float* x    = (const float*)d_in[0];
    const float* wih1 = (const float*)d_in[1];
    const float* whh1 = (const float*)d_in[2];
    const float* bih1 = (const float*)d_in[3];
    const float* bhh1 = (const float*)d_in[4];
    const float* wih2 = (const float*)d_in[5];
    const float* whh2 = (const float*)d_in[6];
    const float* bih2 = (const float*)d_in[7];
    const float* bhh2 = (const float*)d_in[8];
    const float* wih3 = (const float*)d_in[9];
    const float* whh3 = (const float*)d_in[10];
    const float* bih3 = (const float*)d_in[11];
    const float* bhh3 = (const float*)d_in[12];
    const float* wih4 = (const float*)d_in[13];
    const float* whh4 = (const float*)d_in[14];
    const float* bih4 = (const float*)d_in[15];
    const float* bhh4 = (const float*)d_in[16];
    const float* fcw  = (const float*)d_in[17];
    const float* fcb  = (const float*)d_in[18];
    const float* bfcw = (const float*)d_in[19];
    const float* bfcb = (const float*)d_in[20];

    static int attr_done = 0;
    if (!attr_done) {
        cudaFuncSetAttribute(lstm_persist, cudaFuncAttributeMaxDynamicSharedMemorySize, SM_BYTES);
        cudaFuncSetAttribute(fc_kernel, cudaFuncAttributeMaxDynamicSharedMemorySize, FC_SMB);
        attr_done = 1;
    }

    for (int i = 0; i < 3; ++i) noop_kernel<<<1, 32>>>();

    lstm_persist<<<NBLK, NTHR, SM_BYTES>>>(x,
        wih1, whh1, bih1, bhh1, wih2, whh2, bih2, bhh2,
        wih3, whh3, bih3, bhh3, wih4, whh4, bih4, bhh4);

    fc_kernel<<<2*Tm, 256, FC_SMB>>>(fcw, fcb, bfcw, bfcb, (float*)d_out);
}

// round 17
// speedup vs baseline: 1.1209x; 1.1209x over previous
#include <cuda_runtime.h>
#include <cuda_bf16.h>
#include <math.h>
#include <stdint.h>

#define Bm 64
#define Tm 512
#define Hm 512
#define Cm 64
#define NBLK 128
#define NTHR 256
#define KC 128
#define KHP 136                // padded smem row stride (bf16), ==8 mod 64
#define S_WHI 0
#define S_WLO (32*KHP)
#define S_HHI (64*KHP)
#define S_HLO (128*KHP)
#define SLOT_BF (192*KHP)
#define NSLOT 3
#define F_SG   39168
#define F_CS   (F_SG + 4*2048)
#define F_B1   (F_CS + 1024)
#define F_B2   (F_B1 + 32)
#define F_XW   (F_B2 + 32)
#define SM_FLOATS (F_XW + 32)
#define SM_BYTES (SM_FLOATS*4)
#define SQ 260
#define FC_SMB (128*SQ*4)

__device__ __nv_bfloat16 gWh[6][64][32*512];
__device__ __nv_bfloat16 gWl[6][64][32*512];
__device__ __nv_bfloat16 gH1h[2][2][Bm*Hm], gH1l[2][2][Bm*Hm];
__device__ __nv_bfloat16 gH2h[2][2][Bm*Hm], gH2l[2][2][Bm*Hm];
__device__ __nv_bfloat16 gC1h[2][Bm*Hm],    gC1l[2][Bm*Hm];
__device__ float g_hist[2][Tm][Bm*Hm];
// per-dir two-level event barrier: 8 leaves x 8 blocks -> root -> gen
__device__ unsigned g_leaf[2][2][8][32];   // [dir][par][leaf][pad] - 128B-spread leaves
__device__ unsigned g_root[2][2];
__device__ unsigned g_genD[2];

__device__ __forceinline__ float sigf(float v){ return 1.f/(1.f+expf(-v)); }
__device__ __forceinline__ void fma4(float s, const float4 v, float4& a){
    a.x=fmaf(s,v.x,a.x); a.y=fmaf(s,v.y,a.y); a.z=fmaf(s,v.z,a.z); a.w=fmaf(s,v.w,a.w);
}
__device__ __forceinline__ int jrow(int r, int hcb){ return ((r>>3)<<9) + hcb + (r&7); }

__device__ __forceinline__ void ev_arrive(int dir, int par, int gb){
    __threadfence(); __syncthreads();
    if (threadIdx.x == 0) {
        unsigned* leaf = &g_leaf[dir][par][gb >> 3][0];
        if (atomicAdd(leaf, 1u) == 7u) {
            *leaf = 0u;
            __threadfence();
            if (atomicAdd(&g_root[dir][par], 1u) == 7u) {
                g_root[dir][par] = 0u;
                __threadfence();
                atomicAdd(&g_genD[dir], 1u);
            }
        }
    }
}
__device__ __forceinline__ void ev_wait(int dir, unsigned base, unsigned n){
    if (threadIdx.x == 0) {
        while ((int)(*(volatile unsigned*)&g_genD[dir] - base) < (int)n) {}
        __threadfence();
    }
    __syncthreads();
}
__device__ __forceinline__ unsigned smaddr(const void* p){
    unsigned a; asm("{.reg .u64 t; cvta.to.shared.u64 t,%1; cvt.u32.u64 %0,t;}":"=r"(a):"l"(p)); return a;
}
__device__ __forceinline__ void cpa16(unsigned d, const void* s){
    asm volatile("cp.async.cg.shared.global [%0],[%1],16;"::"r"(d),"l"(s));
}
#define CP_COMMIT() asm volatile("cp.async.commit_group;")
#define CP_WAIT1()  asm volatile("cp.async.wait_group 1;" ::: "memory")

__device__ __forceinline__ void ldsm4(uint4& d, unsigned a){
    asm volatile("ldmatrix.sync.aligned.m8n8.x4.shared.b16 {%0,%1,%2,%3},[%4];"
        : "=r"(d.x), "=r"(d.y), "=r"(d.z), "=r"(d.w) : "r"(a));
}
__device__ __forceinline__ void mma16816(float4& c, const uint4 a, const uint2 b){
    asm volatile("mma.sync.aligned.m16n8k16.row.col.f32.bf16.bf16.f32 "
        "{%0,%1,%2,%3},{%4,%5,%6,%7},{%8,%9},{%0,%1,%2,%3};"
        : "+f"(c.x), "+f"(c.y), "+f"(c.z), "+f"(c.w)
        : "r"(a.x), "r"(a.y), "r"(a.z), "r"(a.w), "r"(b.x), "r"(b.y));
}

// branch-free staging (256 threads): 12 unrolled batches of 16 rows;
// region is a compile-time function of the batch index.
__device__ __forceinline__ void pf_chunk(__nv_bfloat16* sb, int slot,
        const __nv_bfloat16* wh, const __nv_bfloat16* wl,
        const __nv_bfloat16* hh, const __nv_bfloat16* hl,
        int k0, int r16, int cc8){
    unsigned db = smaddr(sb) + slot*(SLOT_BF*2);
    int sc = k0 + cc8;
#pragma unroll
    for (int i = 0; i < 12; ++i) {
        int row = r16 + 16*i;
        const __nv_bfloat16* s; unsigned off;
        if (i < 2)      { s = wh + row*512;        off = (S_WHI + row*KHP + cc8)*2; }
        else if (i < 4) { s = wl + (row-32)*512;   off = (S_WLO + (row-32)*KHP + cc8)*2; }
        else if (i < 8) { s = hh + (row-64)*512;   off = (S_HHI + (row-64)*KHP + cc8)*2; }
        else            { s = hl + (row-128)*512;  off = (S_HLO + (row-128)*KHP + cc8)*2; }
        cpa16(db + off, s + sc);
    }
    CP_COMMIT();
}

// one K=128 chunk; warp = M32 x N32 tile at n-offset nb, k-group kg. ldmatrix loads.
__device__ __forceinline__ void gemm_chunk(const __nv_bfloat16* sb, int kg, int nb,
                                           int lane, float4 C[2][4]){
    const int aRow = lane & 15, aK = (lane >> 4) * 8;
    const int bRow = ((lane >> 4) << 3) + (lane & 7), bK = ((lane >> 3) & 1) * 8;
#pragma unroll
    for (int k2 = 0; k2 < 2; ++k2) {
        int kk = (kg*2 + k2)*16;
        uint4 Ah[2], Al[2], Bh2[2], Bl2[2];
#pragma unroll
        for (int i = 0; i < 2; ++i) {
            unsigned pa = smaddr(sb + S_WHI + (16*i + aRow)*KHP + kk + aK);
            ldsm4(Ah[i], pa);
            ldsm4(Al[i], pa + (S_WLO - S_WHI)*2);
        }
#pragma unroll
        for (int h = 0; h < 2; ++h) {
            unsigned pb = smaddr(sb + S_HHI + (nb + h*16 + bRow)*KHP + kk + bK);
            ldsm4(Bh2[h], pb);
            ldsm4(Bl2[h], pb + (S_HLO - S_HHI)*2);
        }
#pragma unroll
        for (int i = 0; i < 2; ++i)
#pragma unroll
            for (int h = 0; h < 2; ++h) {
                uint2 bh0 = make_uint2(Bh2[h].x, Bh2[h].y);
                uint2 bh1 = make_uint2(Bh2[h].z, Bh2[h].w);
                uint2 bl0 = make_uint2(Bl2[h].x, Bl2[h].y);
                uint2 bl1 = make_uint2(Bl2[h].z, Bl2[h].w);
                mma16816(C[i][2*h],   Ah[i], bh0);
                mma16816(C[i][2*h],   Ah[i], bl0);
                mma16816(C[i][2*h],   Al[i], bh0);
                mma16816(C[i][2*h+1], Ah[i], bh1);
                mma16816(C[i][2*h+1], Ah[i], bl1);
                mma16816(C[i][2*h+1], Al[i], bh1);
            }
    }
}

__device__ __forceinline__ void store_C(float* sg, float4 C[2][4], int kg, int nb, int lg, int tg){
#pragma unroll
    for (int i = 0; i < 2; ++i)
#pragma unroll
        for (int nt = 0; nt < 4; ++nt) {
            float* s = sg + kg*2048 + (16*i + lg)*64 + nb + nt*8 + 2*tg;
            *(float2*)s = make_float2(C[i][nt].x, C[i][nt].y);
            *(float2*)(s + 512) = make_float2(C[i][nt].z, C[i][nt].w);
        }
}

__device__ __forceinline__ void cell_phase(float* smf, int tid, int hcb,
        const float* sbias, const float* swih, const float* x, int te,
        float* cstate, __nv_bfloat16* ph_hi, __nv_bfloat16* ph_lo,
        __nv_bfloat16* pc_hi, __nv_bfloat16* pc_lo, float* hist){
    float* sg = smf + F_SG;
    int b = tid & 63, q = tid >> 6;
    float xb = swih ? __ldg(x + b*Tm + te) : 0.f;
    float hv[2], cv[2];
#pragma unroll
    for (int e = 0; e < 2; ++e) {
        int hc = 2*q + e;
        float gs[4];
#pragma unroll
        for (int g = 0; g < 4; ++g) {
            int r = g*8 + hc;
            float v = sg[r*64+b] + sg[2048 + r*64+b] + sg[4096 + r*64+b] + sg[6144 + r*64+b] + sbias[r];
            if (swih) v = fmaf(swih[r], xb, v);
            gs[g] = v;
        }
        float co = cstate[hc*64 + b];
        float cn = sigf(gs[1])*co + sigf(gs[0])*tanhf(gs[2]);
        cstate[hc*64 + b] = cn;
        hv[e] = sigf(gs[3])*tanhf(cn);
        cv[e] = cn;
    }
    int off = b*512 + hcb + 2*q;
    __nv_bfloat16 a0 = __float2bfloat16(hv[0]), a1 = __float2bfloat16(hv[1]);
    *(__nv_bfloat162*)(ph_hi + off) = __halves2bfloat162(a0, a1);
    *(__nv_bfloat162*)(ph_lo + off) =
        __floats2bfloat162_rn(hv[0]-__bfloat162float(a0), hv[1]-__bfloat162float(a1));
    if (pc_hi) {
        __nv_bfloat16 c0 = __float2bfloat16(cv[0]), c1 = __float2bfloat16(cv[1]);
        *(__nv_bfloat162*)(pc_hi + off) = __halves2bfloat162(c0, c1);
        *(__nv_bfloat162*)(pc_lo + off) =
            __floats2bfloat162_rn(cv[0]-__bfloat162float(c0), cv[1]-__bfloat162float(c1));
    }
    if (hist) *(float2*)(hist + off) = make_float2(cv[0], cv[1]);
}

__global__ void noop_kernel() {}

extern "C" __global__ void __launch_bounds__(NTHR, 1)
lstm_persist(const float* __restrict__ x,
             const float* wih1, const float* whh1, const float* bih1, const float* bhh1,
             const float* wih2, const float* whh2, const float* bih2, const float* bhh2,
             const float* wih3, const float* whh3, const float* bih3, const float* bhh3,
             const float* wih4, const float* whh4, const float* bih4, const float* bhh4) {
    extern __shared__ __align__(16) float smf[];
    __nv_bfloat16* sb = (__nv_bfloat16*)smf;

    const int tid = threadIdx.x;
    const int dir = blockIdx.x & 1;
    const int gb  = blockIdx.x >> 1;
    const int hcb = gb << 3;
    const unsigned gbase = *(volatile unsigned*)&g_genD[dir];

    const float* WIH1 = dir ? wih3 : wih1;
    const float* BIH1 = dir ? bih3 : bih1;
    const float* BHH1 = dir ? bhh3 : bhh1;
    const float* BIH2 = dir ? bih4 : bih2;
    const float* BHH2 = dir ? bhh4 : bhh2;
    const float* Wsrc[3] = { dir ? whh3 : whh1, dir ? whh4 : whh2, dir ? wih4 : wih2 };

    if (tid < 32) {
        int j = jrow(tid, hcb);
        smf[F_B1 + tid] = __ldg(BIH1 + j) + __ldg(BHH1 + j);
        smf[F_B2 + tid] = __ldg(BIH2 + j) + __ldg(BHH2 + j);
        smf[F_XW + tid] = __ldg(WIH1 + j);
    }
    for (int i = tid; i < 1024; i += NTHR) smf[F_CS + i] = 0.f;
#pragma unroll 1
    for (int p = 0; p < 3; ++p) {
        int pidx = dir*3 + p;
        for (int idx = tid; idx < 32*512; idx += NTHR) {
            int r = idx >> 9, k = idx & 511;
            float v = __ldg(Wsrc[p] + (size_t)jrow(r, hcb)*512 + k);
            __nv_bfloat16 hi = __float2bfloat16(v);
            gWh[pidx][gb][idx] = hi;
            gWl[pidx][gb][idx] = __float2bfloat16(v - __bfloat162float(hi));
        }
    }
    {   // zero this dir's state planes (64 blocks x 256 threads)
        const int gt = gb*NTHR + tid, stride = 64*NTHR;
        unsigned* z[4] = { (unsigned*)gH1h[dir], (unsigned*)gH1l[dir],
                           (unsigned*)gH2h[dir], (unsigned*)gH2l[dir] };
        for (int a = 0; a < 4; ++a)
            for (int i = gt; i < 2*Bm*Hm/2; i += stride) z[a][i] = 0u;
    }
    ev_arrive(dir, 1, gb);
    ev_wait(dir, gbase, 1);

    const int lane = tid & 31, wid = tid >> 5;
    const int kg = wid >> 1, nb = (wid & 1) * 32;
    const int lg = lane >> 2, tg = lane & 3;
    const int r16 = tid >> 4, pc8 = (tid & 15) * 8;   // staging row/col

    const __nv_bfloat16* wH[3]; const __nv_bfloat16* wL[3];
#pragma unroll
    for (int p = 0; p < 3; ++p) { wH[p] = gWh[dir*3+p][gb]; wL[p] = gWl[dir*3+p][gb]; }

    pf_chunk(sb, 0, wH[0], wL[0], gH1h[dir][1], gH1l[dir][1], 0,  r16, pc8);
    pf_chunk(sb, 1, wH[0], wL[0], gH1h[dir][1], gH1l[dir][1], KC, r16, pc8);

    float4 C[2][4];
#pragma unroll
    for (int i = 0; i < 2; ++i)
#pragma unroll
        for (int nt = 0; nt < 4; ++nt) C[i][nt] = make_float4(0,0,0,0);

#pragma unroll 1
    for (int t = 0; t < Tm; ++t) {
        const int wb = t & 1, rb = wb ^ 1;
        const int te = dir ? (Tm - 1 - t) : t;
        const __nv_bfloat16* hH[3] = { gH1h[dir][rb], gH2h[dir][rb], gC1h[dir] };
        const __nv_bfloat16* hL[3] = { gH1l[dir][rb], gH2l[dir][rb], gC1l[dir] };

#pragma unroll 1
        for (int g = 0; g < 12; ++g) {
            CP_WAIT1(); __syncthreads();
            if (g == 2) ev_wait(dir, gbase, 2u*t + 1u);   // evB(t-1)
            if (g == 6) ev_wait(dir, gbase, 2u*t + 2u);   // evA(t)
            int n = g + 2;
            if (n < 12)
                pf_chunk(sb, n % NSLOT, wH[n>>2], wL[n>>2], hH[n>>2], hL[n>>2], (n & 3)*KC, r16, pc8);
            else if (t + 1 < Tm)
                pf_chunk(sb, n % NSLOT, wH[0], wL[0], gH1h[dir][wb], gH1l[dir][wb], (n-12)*KC, r16, pc8);
            gemm_chunk(sb + (g % NSLOT)*SLOT_BF, kg, nb, lane, C);

            if (g == 3) {
                store_C(smf + F_SG, C, kg, nb, lg, tg);
                __syncthreads();
                cell_phase(smf, tid, hcb, smf + F_B1, smf + F_XW, x, te,
                           smf + F_CS, gH1h[dir][wb], gH1l[dir][wb],
                           gC1h[dir], gC1l[dir], (float*)0);
#pragma unroll
                for (int i = 0; i < 2; ++i)
#pragma unroll
                    for (int nt = 0; nt < 4; ++nt) C[i][nt] = make_float4(0,0,0,0);
                ev_arrive(dir, 0, gb);
            }
            if (g == 11) {
                store_C(smf + F_SG, C, kg, nb, lg, tg);
                __syncthreads();
                cell_phase(smf, tid, hcb, smf + F_B2, (const float*)0, x, te,
                           smf + F_CS + 512, gH2h[dir][wb], gH2l[dir][wb],
                           (__nv_bfloat16*)0, (__nv_bfloat16*)0, g_hist[dir][t]);
#pragma unroll
                for (int i = 0; i < 2; ++i)
#pragma unroll
                    for (int nt = 0; nt < 4; ++nt) C[i][nt] = make_float4(0,0,0,0);
                ev_arrive(dir, 1, gb);
            }
        }
    }
    ev_wait(dir, gbase, 2u*Tm + 1u);
}

// ---- final FC (unchanged) ----
__device__ __forceinline__ void stage_T(const float* __restrict__ src,
                                        float* __restrict__ sT, int tid) {
#pragma unroll
    for (int it = 0; it < 32; ++it) {
        int id = tid + 256*it;
        int lane = id & 31, grp = id >> 5;
        int kl = lane & 7, bg = lane >> 3;
        int kq = ((grp & 15) << 3) | kl;
        int b  = ((grp >> 4) << 2) | bg;
        float4 v = __ldcg((const float4*)(src + b*Hm + (kq << 2)));
        float* p = sT + kq*SQ + b;
        p[0] = v.x; p[64] = v.y; p[128] = v.z; p[192] = v.w;
    }
}

extern "C" __global__ void __launch_bounds__(256)
fc_kernel(const float* __restrict__ fcw, const float* __restrict__ fcb,
          const float* __restrict__ bfcw, const float* __restrict__ bfcb,
          float* __restrict__ out) {
    extern __shared__ __align__(16) float smq[];
    float* sT = smq;
    const int tid = threadIdx.x;
    const int d = blockIdx.x >> 9;
    const int t = blockIdx.x & 511;
    const float* W = d ? bfcw : fcw;
    const float* bias = d ? bfcb : fcb;

    stage_T(W, sT, tid);
    __syncthreads();

    const float* hb = g_hist[d][t];
    const size_t obase = (size_t)d*Bm*Tm*Cm + (size_t)t*Cm;
#pragma unroll
    for (int tt = 0; tt < 4; ++tt) {
        int tile = tid + 256*tt;
        int b = tile >> 4;
        int c0 = (tile & 15) << 2;
        float4 acc = *(const float4*)(bias + c0);
        const float4* hq = (const float4*)(hb + b*Hm);
        const float* wq0 = sT + c0;
#pragma unroll 4
        for (int kq = 0; kq < 128; ++kq) {
            float4 h4 = __ldg(hq + kq);
            const float* wq = wq0 + kq*SQ;
            fma4(h4.x, *(const float4*)(wq), acc);
            fma4(h4.y, *(const float4*)(wq + 64), acc);
            fma4(h4.z, *(const float4*)(wq + 128), acc);
            fma4(h4.w, *(const float4*)(wq + 192), acc);
        }
        *(float4*)(out + obase + (size_t)b*Tm*Cm + c0) = acc;
    }
}

extern "C" void kernel_launch(void* const* d_in, const int* in_sizes, int n_in,
                              void* d_out, int out_size) {
    const float* x    = (const float*)d_in[0];
    const float* wih1 = (const float*)d_in[1];
    const float* whh1 = (const float*)d_in[2];
    const float* bih1 = (const float*)d_in[3];
    const float* bhh1 = (const float*)d_in[4];
    const float* wih2 = (const float*)d_in[5];
    const float* whh2 = (const float*)d_in[6];
    const float* bih2 = (const float*)d_in[7];
    const float* bhh2 = (const float*)d_in[8];
    const float* wih3 = (const float*)d_in[9];
    const float* whh3 = (const float*)d_in[10];
    const float* bih3 = (const float*)d_in[11];
    const float* bhh3 = (const float*)d_in[12];
    const float* wih4 = (const float*)d_in[13];
    const float* whh4 = (const float*)d_in[14];
    const float* bih4 = (const float*)d_in[15];
    const float* bhh4 = (const float*)d_in[16];
    const float* fcw  = (const float*)d_in[17];
    const float* fcb  = (const float*)d_in[18];
    const float* bfcw = (const float*)d_in[19];
    const float* bfcb = (const float*)d_in[20];

    static int attr_done = 0;
    if (!attr_done) {
        cudaFuncSetAttribute(lstm_persist, cudaFuncAttributeMaxDynamicSharedMemorySize, SM_BYTES);
        cudaFuncSetAttribute(fc_kernel, cudaFuncAttributeMaxDynamicSharedMemorySize, FC_SMB);
        attr_done = 1;
    }

    for (int i = 0; i < 3; ++i) noop_kernel<<<1, 32>>>();

    lstm_persist<<<NBLK, NTHR, SM_BYTES>>>(x,
        wih1, whh1, bih1, bhh1, wih2, whh2, bih2, bhh2,
        wih3, whh3, bih3, bhh3, wih4, whh4, bih4, bhh4);

    fc_kernel<<<2*Tm, 256, FC_SMB>>>(fcw, fcb, bfcw, bfcb, (float*)d_out);
}